// round 12
// baseline (speedup 1.0000x reference)
#include <cuda_runtime.h>
#include <math.h>

#define B_   32
#define TT_  512
#define TM_  2048
#define D_   512
#define M_   80
#define NEGF (-1e9f)

#define HEXP_ELEMS (B_*TM_*D_)       /* 33554432 */
#define LOSS_OFF   HEXP_ELEMS
#define DUR_OFF    (HEXP_ELEMS + 1)

typedef unsigned long long ull;

// ------------------- device scratch (no allocation allowed) -------------------
__device__ float g_hw[B_*TT_*M_];         // [b*Tt+i][80] = h @ W
__device__ float g_hb[B_*TT_];            // h @ b_proj
__device__ float g_S[(size_t)B_*TM_*TT_]; // [b][j][i] masked scores (128 MB)
__device__ int   g_idx[B_*TM_];           // frame -> token index
__device__ float g_lsq[B_];
__device__ float g_lcnt[B_];

// ------------------- f32x2 helpers -------------------
__device__ __forceinline__ ull pk2(float x, float y) {
    ull r;
    asm("mov.b64 %0, {%1,%2};" : "=l"(r) : "f"(x), "f"(y));
    return r;
}
__device__ __forceinline__ float2 upk2(ull v) {
    float2 r;
    asm("mov.b64 {%0,%1}, %2;" : "=f"(r.x), "=f"(r.y) : "l"(v));
    return r;
}
#define FMA2(d, a, b, c) asm("fma.rn.f32x2 %0, %1, %2, %3;" : "=l"(d) : "l"(a), "l"(b), "l"(c))

// =================== K1: hw[b,i,m] = sum_d h[b,i,d] * w[d,m]  (frozen) ===================
__global__ void __launch_bounds__(256) k1_hw(const float* __restrict__ h,
                                             const float* __restrict__ w) {
    __shared__ float hS[64*68];   // [r][d] stride 68
    __shared__ float wS[64*84];   // [d][m] stride 84
    int tid  = threadIdx.x;
    int row0 = blockIdx.x * 64;
    int tx = tid & 15;
    int ty = tid >> 4;
    float acc[4][5];
#pragma unroll
    for (int r = 0; r < 4; r++)
#pragma unroll
        for (int m = 0; m < 5; m++) acc[r][m] = 0.f;

    for (int dc = 0; dc < D_; dc += 64) {
#pragma unroll
        for (int k = 0; k < 4; k++) {
            int l = tid + k*256;
            int r = l >> 4, d4 = l & 15;
            float4 v = *(const float4*)&h[(size_t)(row0 + r)*D_ + dc + d4*4];
            *(float4*)&hS[r*68 + d4*4] = v;
        }
#pragma unroll
        for (int k = 0; k < 5; k++) {
            int l = tid + k*256;
            int d = l / 20, m4 = l % 20;
            float4 v = *(const float4*)&w[(size_t)(dc + d)*M_ + m4*4];
            *(float4*)&wS[d*84 + m4*4] = v;
        }
        __syncthreads();
#pragma unroll 8
        for (int d = 0; d < 64; d++) {
            float a0 = hS[(ty*4+0)*68 + d];
            float a1 = hS[(ty*4+1)*68 + d];
            float a2 = hS[(ty*4+2)*68 + d];
            float a3 = hS[(ty*4+3)*68 + d];
#pragma unroll
            for (int m = 0; m < 5; m++) {
                float bv = wS[d*84 + tx*5 + m];
                acc[0][m] += a0*bv; acc[1][m] += a1*bv;
                acc[2][m] += a2*bv; acc[3][m] += a3*bv;
            }
        }
        __syncthreads();
    }
#pragma unroll
    for (int r = 0; r < 4; r++)
#pragma unroll
        for (int m = 0; m < 5; m++)
            g_hw[(size_t)(row0 + ty*4 + r)*M_ + tx*5 + m] = acc[r][m];
}

// =================== K1b: hb[row] = h[row,:] . b_proj  (frozen) ===================
__global__ void k1_hb(const float* __restrict__ h, const float* __restrict__ bp) {
    int gw   = (blockIdx.x*blockDim.x + threadIdx.x) >> 5;
    int lane = threadIdx.x & 31;
    if (gw >= B_*TT_) return;
    const float4* hr = (const float4*)&h[(size_t)gw * D_];
    const float4* b4 = (const float4*)bp;
    float s = 0.f;
    for (int k = lane; k < D_/4; k += 32) {
        float4 a = hr[k], c = b4[k];
        s += a.x*c.x + a.y*c.y + a.z*c.z + a.w*c.w;
    }
#pragma unroll
    for (int o = 16; o; o >>= 1) s += __shfl_down_sync(0xffffffffu, s, o);
    if (lane == 0) g_hb[gw] = s;
}

// =================== K2: S[b][j][i] = masked(hw . mel + hb)  (frozen) ===================
__global__ void __launch_bounds__(256) k2_attn(const float* __restrict__ mel,
                                               const int* __restrict__ tlv,
                                               const int* __restrict__ mlv) {
    extern __shared__ float sm2[];
    float* melS = sm2;            // [80][132]
    float* hwS  = sm2 + 80*132;   // [80][129]
    int b  = blockIdx.z;
    int ml = mlv[b];
    int j0 = blockIdx.y * 128;
    if (j0 >= ml) return;
    int i0  = blockIdx.x * 128;
    int tid = threadIdx.x;
    int tx  = tid & 15;
    int ty  = tid >> 4;

    const float* melB = mel + (size_t)b*M_*TM_;
#pragma unroll
    for (int k = 0; k < 10; k++) {
        int l = tid + k*256;
        int m = l >> 5, j4 = l & 31;
        float4 v = *(const float4*)&melB[(size_t)m*TM_ + j0 + j4*4];
        *(float4*)&melS[m*132 + j4*4] = v;
    }
    const float* hwB = g_hw + (size_t)b*TT_*M_;
#pragma unroll
    for (int k = 0; k < 40; k++) {
        int l = tid + k*256;
        int m = l % 80, ii = l / 80;
        hwS[m*129 + ii] = hwB[(size_t)(i0+ii)*M_ + m];
    }
    __syncthreads();

    ull acc[8][4];
#pragma unroll
    for (int jk = 0; jk < 8; jk++)
#pragma unroll
        for (int p = 0; p < 4; p++) acc[jk][p] = 0ull;

#pragma unroll 2
    for (int m = 0; m < M_; m++) {
        float hv[8];
#pragma unroll
        for (int k = 0; k < 8; k++) hv[k] = hwS[m*129 + tx + 16*k];
        ull hp[4];
#pragma unroll
        for (int p = 0; p < 4; p++) hp[p] = pk2(hv[2*p], hv[2*p+1]);
#pragma unroll
        for (int jk = 0; jk < 8; jk++) {
            float mv = melS[m*132 + ty + 16*jk];
            ull mp = pk2(mv, mv);
#pragma unroll
            for (int p = 0; p < 4; p++) FMA2(acc[jk][p], hp[p], mp, acc[jk][p]);
        }
    }

    int tlb = tlv[b];
    float hbv[8];
    bool  msk[8];
#pragma unroll
    for (int k = 0; k < 8; k++) {
        int ig = i0 + tx + 16*k;
        hbv[k] = g_hb[b*TT_ + ig];
        msk[k] = (ig < tlb);
    }
#pragma unroll
    for (int jk = 0; jk < 8; jk++) {
        int j = j0 + ty + 16*jk;
        if (j < ml) {
            float* row = g_S + ((size_t)b*TM_ + j)*TT_ + i0;
#pragma unroll
            for (int p = 0; p < 4; p++) {
                float2 v = upk2(acc[jk][p]);
                int k0 = 2*p, k1 = 2*p + 1;
                row[tx + 16*k0] = msk[k0] ? (v.x + hbv[k0]) : NEGF;
                row[tx + 16*k1] = msk[k1] ? (v.y + hbv[k1]) : NEGF;
            }
        }
    }
}

// =================== K3: MAS DP — R5 protocol, 4 warps, 4 rows/thread ===================
// 128 threads; thread t owns rows 4t..4t+3 (q0..q3). ALL warps on the same column.
// Per column: lane31 stores q3 (pre-update) into parity smem slot -> ONE __syncthreads
// -> shfl_up / smem-boundary read -> 4 independent row updates. Rolling choice bits
// (cw = 2cw + take). One coalesced LDG.128/thread/column, 8-deep constant-indexed ring.
// Warps whose rows are all >= text_len skip math (barrier kept).
__global__ void __launch_bounds__(128) k3_dp(const float* __restrict__ ldp,
                                             const int* __restrict__ tlv,
                                             const int* __restrict__ mlv,
                                             float* __restrict__ out) {
    extern __shared__ unsigned int dsm3[];
    unsigned int* ch   = dsm3;                 // [64][4][128] choice words
    unsigned int* dur  = dsm3 + 64*4*128;      // [512]
    unsigned int* wsum = dur + 512;            // [4]
    float*        red  = (float*)(wsum + 4);   // [4]
    float*        bnd  = (float*)(red + 4);    // [2][4] parity-buffered boundary q3

    int b    = blockIdx.x;
    int tid  = threadIdx.x;
    int lane = tid & 31, w = tid >> 5;
    int tl = tlv[b], ml = mlv[b];
    int jlim = ml - 1;
    const float*  Sb  = g_S + (size_t)b*TM_*TT_;
    const float4* Sb4 = (const float4*)Sb;     // column j: Sb4[j*128 + tid]

    bool wact = (w << 7) < tl;                 // warp has at least one row < tl

    float q0 = NEGF, q1 = NEGF, q2 = NEGF, q3 = NEGF;
    unsigned int cw0 = 0u, cw1 = 0u, cw2 = 0u, cw3 = 0u;
    if (tid == 0) q0 = Sb[0];

#pragma unroll
    for (int r = 0; r < 4; r++) dur[tid*4 + r] = 0u;

    // 8-deep prefetch ring (constant indexing only)
    float4 buf[8];
#pragma unroll
    for (int u = 0; u < 8; u++) {              // ml >= 1024, so 1..8 are valid columns
        if (wact) buf[u] = Sb4[(size_t)(1 + u)*128 + tid];
    }
    __syncthreads();

    int ngroups = (jlim + 7) >> 3;             // 8-column groups covering j = 1..jlim
    for (int g = 0; g < ngroups; g++) {
        int jbase = 1 + (g << 3);
#pragma unroll
        for (int u = 0; u < 8; u++) {
            int j = jbase + u;
            if (j <= jlim) {                   // block-uniform
                int par = (j & 1) << 2;
                if (wact && lane == 31) bnd[par + w] = q3;   // pre-update q3
                __syncthreads();
                if (wact) {
                    float sh = __shfl_up_sync(0xffffffffu, q3, 1);
                    float top = (lane == 0)
                                ? ((w == 0) ? NEGF : bnd[par + (w - 1)])
                                : sh;
                    float4 c = buf[u];
                    unsigned int t0 = (top > q0) ? 1u : 0u;
                    unsigned int t1 = (q0 > q1) ? 1u : 0u;
                    unsigned int t2 = (q1 > q2) ? 1u : 0u;
                    unsigned int t3 = (q2 > q3) ? 1u : 0u;
                    float n0 = c.x + fmaxf(q0, top);
                    float n1 = c.y + fmaxf(q1, q0);
                    float n2 = c.z + fmaxf(q2, q1);
                    float n3 = c.w + fmaxf(q3, q2);
                    q0 = n0; q1 = n1; q2 = n2; q3 = n3;
                    cw0 = cw0 + cw0 + t0;
                    cw1 = cw1 + cw1 + t1;
                    cw2 = cw2 + cw2 + t2;
                    cw3 = cw3 + cw3 + t3;
                    if ((j & 31) == 31) {
                        unsigned int* cr = ch + (j >> 5)*512 + tid;
                        cr[0] = cw0; cr[128] = cw1; cr[256] = cw2; cr[384] = cw3;
                        cw0 = cw1 = cw2 = cw3 = 0u;
                    }
                    int jn = j + 8; if (jn > jlim) jn = jlim;
                    buf[u] = Sb4[(size_t)jn*128 + tid];
                }
            }
        }
    }
    if (wact && ((jlim & 31) != 31)) {          // normalize partial word
        int sh = 31 - (jlim & 31);
        unsigned int* cr = ch + (jlim >> 5)*512 + tid;
        cr[0] = cw0 << sh; cr[128] = cw1 << sh; cr[256] = cw2 << sh; cr[384] = cw3 << sh;
    }
    __syncthreads();

    if (tid == 0) {                             // serial run-scan backtrack (ffs on reversed bits)
        int ii = tl - 1, jj = ml - 1;
        while (jj >= 0) {
            if (ii == 0) { dur[0] += (unsigned)(jj + 1); break; }
            unsigned int wv = ch[(jj >> 5)*512 + (ii & 3)*128 + (ii >> 2)];
            int bi = 31 - (jj & 31);            // bit index of column jj
            unsigned int wm = wv & (0xFFFFFFFFu << bi);
            if (wm == 0u) {
                int steps = (jj & 31) + 1;
                dur[ii] += (unsigned)steps;
                jj -= steps;
            } else {
                int bit = __ffs(wm) - 1;        // lowest set bit >= bi -> largest column <= jj
                int jp  = (jj & ~31) + (31 - bit);
                dur[ii] += (unsigned)(jj - jp + 1);
                ii -= 1;
                jj = jp - 1;
            }
        }
    }
    __syncthreads();

    // ---- outputs: durations, loss partial, idx scatter ----
    unsigned int dv[4], tot = 0;
#pragma unroll
    for (int r = 0; r < 4; r++) { dv[r] = dur[tid*4 + r]; tot += dv[r]; }

    float ls = 0.f;
#pragma unroll
    for (int r = 0; r < 4; r++) {
        int row = tid*4 + r;
        out[DUR_OFF + b*TT_ + row] = (float)dv[r];
        if (row < tl) {
            float lg = logf(fmaxf((float)dv[r], 1.0f));
            float df = ldp[b*TT_ + row] - lg;
            ls += df * df;
        }
    }
#pragma unroll
    for (int o = 16; o; o >>= 1) ls += __shfl_down_sync(0xffffffffu, ls, o);
    if (lane == 0) red[w] = ls;

    unsigned int v = tot;
#pragma unroll
    for (int o = 1; o < 32; o <<= 1) {
        unsigned int t = __shfl_up_sync(0xffffffffu, v, o);
        if (lane >= o) v += t;
    }
    if (lane == 31) wsum[w] = v;
    __syncthreads();
    if (tid == 0) {
        g_lsq[b]  = red[0] + red[1] + red[2] + red[3];
        g_lcnt[b] = (float)tl;
    }
    unsigned int off = 0;
#pragma unroll
    for (int k = 0; k < 4; k++) if (k < w) off += wsum[k];
    unsigned int pos = off + v - tot;           // exclusive prefix over rows
#pragma unroll
    for (int r = 0; r < 4; r++) {
        for (unsigned int kk = 0; kk < dv[r]; kk++) g_idx[b*TM_ + pos + kk] = tid*4 + r;
        pos += dv[r];
    }
}

// =================== K5: length-regulate expansion (+ fused loss reduce) ===================
__global__ void __launch_bounds__(256) k5_expand(const float* __restrict__ h,
                                                 const int* __restrict__ mlv,
                                                 float* __restrict__ out) {
    if (blockIdx.y == 0 && blockIdx.z == 0 && threadIdx.x < 32) {
        float s = g_lsq[threadIdx.x], cc = g_lcnt[threadIdx.x];
#pragma unroll
        for (int o = 16; o; o >>= 1) {
            s  += __shfl_down_sync(0xffffffffu, s, o);
            cc += __shfl_down_sync(0xffffffffu, cc, o);
        }
        if (threadIdx.x == 0) out[LOSS_OFF] = s / cc;
    }
    int b  = blockIdx.z;
    int j  = blockIdx.y * 2 + (threadIdx.x >> 7);
    int c4 = threadIdx.x & 127;
    int ml = mlv[b];
    float4 v;
    if (j < ml) {
        int idx = g_idx[b*TM_ + j];
        v = *(const float4*)&h[((size_t)(b*TT_ + idx))*D_ + c4*4];
    } else {
        v = make_float4(0.f, 0.f, 0.f, 0.f);
    }
    *(float4*)&out[((size_t)(b*TM_ + j))*D_ + c4*4] = v;
}

// =================== host launcher ===================
extern "C" void kernel_launch(void* const* d_in, const int* in_sizes, int n_in,
                              void* d_out, int out_size) {
    const float* h_text = (const float*)d_in[0];   // [32,512,512]
    const float* mel    = (const float*)d_in[1];   // [32,80,2048]
    const int*   tl     = (const int*)  d_in[2];   // [32]
    const int*   mlv    = (const int*)  d_in[3];   // [32]
    const float* w_proj = (const float*)d_in[4];   // [512,80]
    const float* b_proj = (const float*)d_in[5];   // [512]
    const float* ldp    = (const float*)d_in[6];   // [32,512]
    float* out = (float*)d_out;

    const int K2_SMEM = (80*132 + 80*129) * 4;                 // 83520
    const int K3_SMEM = (64*4*128 + 512 + 4 + 4 + 8) * 4;      // 133232
    cudaFuncSetAttribute(k2_attn, cudaFuncAttributeMaxDynamicSharedMemorySize, K2_SMEM);
    cudaFuncSetAttribute(k3_dp,   cudaFuncAttributeMaxDynamicSharedMemorySize, K3_SMEM);

    k1_hw<<<256, 256>>>(h_text, w_proj);            // launch 1
    k1_hb<<<2048, 256>>>(h_text, b_proj);           // launch 2
    k2_attn<<<dim3(4, 16, 32), 256, K2_SMEM>>>(mel, tl, mlv);   // launch 3
    k3_dp<<<32, 128, K3_SMEM>>>(ldp, tl, mlv, out); // launch 4  <- ncu captures this
    k5_expand<<<dim3(1, 1024, 32), 256>>>(h_text, mlv, out);    // launch 5
}

// round 13
// speedup vs baseline: 2.6572x; 2.6572x over previous
#include <cuda_runtime.h>
#include <math.h>

#define B_   32
#define TT_  512
#define TM_  2048
#define D_   512
#define M_   80
#define NEGF (-1e9f)

#define HEXP_ELEMS (B_*TM_*D_)       /* 33554432 */
#define LOSS_OFF   HEXP_ELEMS
#define DUR_OFF    (HEXP_ELEMS + 1)

typedef unsigned long long ull;

// ------------------- device scratch (no allocation allowed) -------------------
__device__ float g_hw[B_*TT_*M_];         // [b*Tt+i][80] = h @ W
__device__ float g_hb[B_*TT_];            // h @ b_proj
__device__ float g_S[(size_t)B_*TM_*TT_]; // [b][j][i] masked scores (128 MB)
__device__ int   g_idx[B_*TM_];           // frame -> token index
__device__ float g_lsq[B_];
__device__ float g_lcnt[B_];

// ------------------- f32x2 helpers -------------------
__device__ __forceinline__ ull pk2(float x, float y) {
    ull r;
    asm("mov.b64 %0, {%1,%2};" : "=l"(r) : "f"(x), "f"(y));
    return r;
}
__device__ __forceinline__ float2 upk2(ull v) {
    float2 r;
    asm("mov.b64 {%0,%1}, %2;" : "=f"(r.x), "=f"(r.y) : "l"(v));
    return r;
}
#define FMA2(d, a, b, c) asm("fma.rn.f32x2 %0, %1, %2, %3;" : "=l"(d) : "l"(a), "l"(b), "l"(c))

// =================== K1: hw[b,i,m] = sum_d h[b,i,d] * w[d,m]  (frozen R5) ===================
__global__ void __launch_bounds__(256) k1_hw(const float* __restrict__ h,
                                             const float* __restrict__ w) {
    __shared__ float hS[64*68];   // [r][d] stride 68
    __shared__ float wS[64*84];   // [d][m] stride 84
    int tid  = threadIdx.x;
    int row0 = blockIdx.x * 64;
    int tx = tid & 15;
    int ty = tid >> 4;
    float acc[4][5];
#pragma unroll
    for (int r = 0; r < 4; r++)
#pragma unroll
        for (int m = 0; m < 5; m++) acc[r][m] = 0.f;

    for (int dc = 0; dc < D_; dc += 64) {
#pragma unroll
        for (int k = 0; k < 4; k++) {
            int l = tid + k*256;
            int r = l >> 4, d4 = l & 15;
            float4 v = *(const float4*)&h[(size_t)(row0 + r)*D_ + dc + d4*4];
            *(float4*)&hS[r*68 + d4*4] = v;
        }
#pragma unroll
        for (int k = 0; k < 5; k++) {
            int l = tid + k*256;
            int d = l / 20, m4 = l % 20;
            float4 v = *(const float4*)&w[(size_t)(dc + d)*M_ + m4*4];
            *(float4*)&wS[d*84 + m4*4] = v;
        }
        __syncthreads();
#pragma unroll 8
        for (int d = 0; d < 64; d++) {
            float a0 = hS[(ty*4+0)*68 + d];
            float a1 = hS[(ty*4+1)*68 + d];
            float a2 = hS[(ty*4+2)*68 + d];
            float a3 = hS[(ty*4+3)*68 + d];
#pragma unroll
            for (int m = 0; m < 5; m++) {
                float bv = wS[d*84 + tx*5 + m];
                acc[0][m] += a0*bv; acc[1][m] += a1*bv;
                acc[2][m] += a2*bv; acc[3][m] += a3*bv;
            }
        }
        __syncthreads();
    }
#pragma unroll
    for (int r = 0; r < 4; r++)
#pragma unroll
        for (int m = 0; m < 5; m++)
            g_hw[(size_t)(row0 + ty*4 + r)*M_ + tx*5 + m] = acc[r][m];
}

// =================== K1b: hb[row] = h[row,:] . b_proj  (frozen R5) ===================
__global__ void k1_hb(const float* __restrict__ h, const float* __restrict__ bp) {
    int gw   = (blockIdx.x*blockDim.x + threadIdx.x) >> 5;
    int lane = threadIdx.x & 31;
    if (gw >= B_*TT_) return;
    const float4* hr = (const float4*)&h[(size_t)gw * D_];
    const float4* b4 = (const float4*)bp;
    float s = 0.f;
    for (int k = lane; k < D_/4; k += 32) {
        float4 a = hr[k], c = b4[k];
        s += a.x*c.x + a.y*c.y + a.z*c.z + a.w*c.w;
    }
#pragma unroll
    for (int o = 16; o; o >>= 1) s += __shfl_down_sync(0xffffffffu, s, o);
    if (lane == 0) g_hb[gw] = s;
}

// =================== K2: S[b][j][i] = masked(hw . mel + hb)  (frozen R5) ===================
__global__ void __launch_bounds__(256) k2_attn(const float* __restrict__ mel,
                                               const int* __restrict__ tlv,
                                               const int* __restrict__ mlv) {
    extern __shared__ float sm2[];
    float* melS = sm2;            // [80][132]
    float* hwS  = sm2 + 80*132;   // [80][129]
    int b  = blockIdx.z;
    int ml = mlv[b];
    int j0 = blockIdx.y * 128;
    if (j0 >= ml) return;
    int i0  = blockIdx.x * 128;
    int tid = threadIdx.x;
    int tx  = tid & 15;
    int ty  = tid >> 4;

    const float* melB = mel + (size_t)b*M_*TM_;
#pragma unroll
    for (int k = 0; k < 10; k++) {
        int l = tid + k*256;
        int m = l >> 5, j4 = l & 31;
        float4 v = *(const float4*)&melB[(size_t)m*TM_ + j0 + j4*4];
        *(float4*)&melS[m*132 + j4*4] = v;
    }
    const float* hwB = g_hw + (size_t)b*TT_*M_;
#pragma unroll
    for (int k = 0; k < 40; k++) {
        int l = tid + k*256;
        int m = l % 80, ii = l / 80;
        hwS[m*129 + ii] = hwB[(size_t)(i0+ii)*M_ + m];
    }
    __syncthreads();

    ull acc[8][4];
#pragma unroll
    for (int jk = 0; jk < 8; jk++)
#pragma unroll
        for (int p = 0; p < 4; p++) acc[jk][p] = 0ull;

#pragma unroll 2
    for (int m = 0; m < M_; m++) {
        float hv[8];
#pragma unroll
        for (int k = 0; k < 8; k++) hv[k] = hwS[m*129 + tx + 16*k];
        ull hp[4];
#pragma unroll
        for (int p = 0; p < 4; p++) hp[p] = pk2(hv[2*p], hv[2*p+1]);
#pragma unroll
        for (int jk = 0; jk < 8; jk++) {
            float mv = melS[m*132 + ty + 16*jk];
            ull mp = pk2(mv, mv);
#pragma unroll
            for (int p = 0; p < 4; p++) FMA2(acc[jk][p], hp[p], mp, acc[jk][p]);
        }
    }

    int tlb = tlv[b];
    float hbv[8];
    bool  msk[8];
#pragma unroll
    for (int k = 0; k < 8; k++) {
        int ig = i0 + tx + 16*k;
        hbv[k] = g_hb[b*TT_ + ig];
        msk[k] = (ig < tlb);
    }
#pragma unroll
    for (int jk = 0; jk < 8; jk++) {
        int j = j0 + ty + 16*jk;
        if (j < ml) {
            float* row = g_S + ((size_t)b*TM_ + j)*TT_ + i0;
#pragma unroll
            for (int p = 0; p < 4; p++) {
                float2 v = upk2(acc[jk][p]);
                int k0 = 2*p, k1 = 2*p + 1;
                row[tx + 16*k0] = msk[k0] ? (v.x + hbv[k0]) : NEGF;
                row[tx + 16*k1] = msk[k1] ? (v.y + hbv[k1]) : NEGF;
            }
        }
    }
}

// =================== K3: MAS DP + backtrack — R5 VERBATIM (measured 253 µs) ===================
// grid 32 (one block per batch), 512 threads, dynamic smem ~135.4 KB.
__global__ void __launch_bounds__(512) k3_dp(const float* __restrict__ ldp,
                                             const int* __restrict__ tlv,
                                             const int* __restrict__ mlv,
                                             float* __restrict__ out) {
    extern __shared__ unsigned int dsm[];
    unsigned int* ch   = dsm;                         // [512][65]
    float*        bnd  = (float*)(dsm + 512*65);      // [2][16]
    unsigned int* dur  = (unsigned int*)(bnd + 32);   // [512]
    unsigned int* wsum = dur + 512;                   // [16]
    float*        red  = (float*)(wsum + 16);         // [16]

    int b    = blockIdx.x;
    int i    = threadIdx.x;
    int lane = i & 31, wid = i >> 5;
    int tl = tlv[b], ml = mlv[b];
    const float* Sb = g_S + (size_t)b*TM_*TT_;

    float q = (i == 0) ? Sb[0] : NEGF;
    unsigned int cw = 0;
    int p = 0;
    float c[8], n[8];
#pragma unroll
    for (int k = 0; k < 8; k++) {
        int j = 1 + k;
        c[k] = (j < ml) ? Sb[(size_t)j*TT_ + i] : 0.f;
    }

    for (int j0 = 1; j0 < ml; j0 += 8) {
#pragma unroll
        for (int k = 0; k < 8; k++) {          // prefetch next group
            int j = j0 + 8 + k;
            n[k] = (j < ml) ? Sb[(size_t)j*TT_ + i] : 0.f;
        }
#pragma unroll
        for (int k = 0; k < 8; k++) {
            int j = j0 + k;
            if (j < ml) {                       // uniform across block
                if (lane == 31) bnd[p*16 + wid] = q;
                __syncthreads();
                float up = __shfl_up_sync(0xffffffffu, q, 1);
                if (lane == 0) up = (wid == 0) ? NEGF : bnd[p*16 + wid - 1];
                unsigned int take = (up > q) ? 1u : 0u;
                q = c[k] + fmaxf(q, up);
                cw |= take << (j & 31);
                if ((j & 31) == 31) { ch[i*65 + (j >> 5)] = cw; cw = 0; }
                p ^= 1;
            }
        }
#pragma unroll
        for (int k = 0; k < 8; k++) c[k] = n[k];
    }
    if (((ml - 1) & 31) != 31) ch[i*65 + ((ml - 1) >> 5)] = cw;
    dur[i] = 0;
    __syncthreads();

    if (i == 0) {                               // serial CLZ run-scan backtrack
        int ii = tl - 1, j = ml - 1;
        while (j >= 0) {
            if (ii == 0) { dur[0] += (unsigned)(j + 1); break; }
            unsigned int w = ch[ii*65 + (j >> 5)];
            int bit = j & 31;
            if (bit != 31) w &= (2u << bit) - 1u;
            if (w == 0) { dur[ii] += (unsigned)(bit + 1); j -= bit + 1; }
            else {
                int hb = 31 - __clz(w);
                int jp = (j & ~31) + hb;
                dur[ii] += (unsigned)(j - jp + 1);
                ii -= 1;
                j = jp - 1;
            }
        }
    }
    __syncthreads();

    unsigned int d = dur[i];
    out[DUR_OFF + b*TT_ + i] = (float)d;

    // loss partial
    float part = 0.f;
    if (i < tl) {
        float lg = logf(fmaxf((float)d, 1.0f));
        float df = ldp[b*TT_ + i] - lg;
        part = df * df;
    }
#pragma unroll
    for (int o = 16; o; o >>= 1) part += __shfl_down_sync(0xffffffffu, part, o);
    if (lane == 0) red[wid] = part;

    // inclusive scan of dur -> frame index scatter
    unsigned int v = d;
#pragma unroll
    for (int o = 1; o < 32; o <<= 1) {
        unsigned int t = __shfl_up_sync(0xffffffffu, v, o);
        if (lane >= o) v += t;
    }
    if (lane == 31) wsum[wid] = v;
    __syncthreads();
    if (i < 16) {
        unsigned int s = wsum[i];
#pragma unroll
        for (int o = 1; o < 16; o <<= 1) {
            unsigned int t = __shfl_up_sync(0x0000ffffu, s, o);
            if ((i & 15) >= o) s += t;
        }
        wsum[i] = s;
        float ls = red[i];
#pragma unroll
        for (int o = 8; o; o >>= 1) ls += __shfl_down_sync(0x0000ffffu, ls, o);
        if (i == 0) { g_lsq[b] = ls; g_lcnt[b] = (float)tl; }
    }
    __syncthreads();
    unsigned int base = (wid == 0) ? 0u : wsum[wid - 1];
    unsigned int cend = base + v;
    unsigned int cstart = cend - d;
    for (unsigned int j = cstart; j < cend; j++) g_idx[b*TM_ + j] = i;
}

// =================== K5: length-regulate expansion (+ fused loss reduce, R11) ===================
__global__ void __launch_bounds__(256) k5_expand(const float* __restrict__ h,
                                                 const int* __restrict__ mlv,
                                                 float* __restrict__ out) {
    if (blockIdx.y == 0 && blockIdx.z == 0 && threadIdx.x < 32) {
        float s = g_lsq[threadIdx.x], cc = g_lcnt[threadIdx.x];
#pragma unroll
        for (int o = 16; o; o >>= 1) {
            s  += __shfl_down_sync(0xffffffffu, s, o);
            cc += __shfl_down_sync(0xffffffffu, cc, o);
        }
        if (threadIdx.x == 0) out[LOSS_OFF] = s / cc;
    }
    int b  = blockIdx.z;
    int j  = blockIdx.y * 2 + (threadIdx.x >> 7);
    int c4 = threadIdx.x & 127;
    int ml = mlv[b];
    float4 v;
    if (j < ml) {
        int idx = g_idx[b*TM_ + j];
        v = *(const float4*)&h[((size_t)(b*TT_ + idx))*D_ + c4*4];
    } else {
        v = make_float4(0.f, 0.f, 0.f, 0.f);
    }
    *(float4*)&out[((size_t)(b*TM_ + j))*D_ + c4*4] = v;
}

// =================== host launcher ===================
extern "C" void kernel_launch(void* const* d_in, const int* in_sizes, int n_in,
                              void* d_out, int out_size) {
    const float* h_text = (const float*)d_in[0];   // [32,512,512]
    const float* mel    = (const float*)d_in[1];   // [32,80,2048]
    const int*   tl     = (const int*)  d_in[2];   // [32]
    const int*   mlv    = (const int*)  d_in[3];   // [32]
    const float* w_proj = (const float*)d_in[4];   // [512,80]
    const float* b_proj = (const float*)d_in[5];   // [512]
    const float* ldp    = (const float*)d_in[6];   // [32,512]
    float* out = (float*)d_out;

    const int K2_SMEM = (80*132 + 80*129) * 4;                        // 83520
    const int K3_SMEM = (512*65 + 512 + 16 + 16) * 4 + 32 * 4;        // 135456
    cudaFuncSetAttribute(k2_attn, cudaFuncAttributeMaxDynamicSharedMemorySize, K2_SMEM);
    cudaFuncSetAttribute(k3_dp,   cudaFuncAttributeMaxDynamicSharedMemorySize, K3_SMEM);

    k1_hw<<<256, 256>>>(h_text, w_proj);            // launch 1
    k1_hb<<<2048, 256>>>(h_text, b_proj);           // launch 2
    k2_attn<<<dim3(4, 16, 32), 256, K2_SMEM>>>(mel, tl, mlv);   // launch 3
    k3_dp<<<32, 512, K3_SMEM>>>(ldp, tl, mlv, out); // launch 4
    k5_expand<<<dim3(1, 1024, 32), 256>>>(h_text, mlv, out);    // launch 5
}

// round 14
// speedup vs baseline: 2.7696x; 1.0423x over previous
#include <cuda_runtime.h>
#include <math.h>

#define B_   32
#define TT_  512
#define TM_  2048
#define D_   512
#define M_   80
#define NEGF (-1e9f)

#define HEXP_ELEMS (B_*TM_*D_)       /* 33554432 */
#define LOSS_OFF   HEXP_ELEMS
#define DUR_OFF    (HEXP_ELEMS + 1)

typedef unsigned long long ull;

// ------------------- device scratch (no allocation allowed) -------------------
__device__ float g_hw[B_*TT_*M_];         // [b*Tt+i][80] = h @ W
__device__ float g_hb[B_*TT_];            // h @ b_proj
__device__ float g_S[(size_t)B_*TM_*TT_]; // [b][j][i] masked scores (128 MB)
__device__ int   g_idx[B_*TM_];           // frame -> token index
__device__ float g_lsq[B_];
__device__ float g_lcnt[B_];

// ------------------- f32x2 helpers -------------------
__device__ __forceinline__ ull pk2(float x, float y) {
    ull r;
    asm("mov.b64 %0, {%1,%2};" : "=l"(r) : "f"(x), "f"(y));
    return r;
}
__device__ __forceinline__ float2 upk2(ull v) {
    float2 r;
    asm("mov.b64 {%0,%1}, %2;" : "=f"(r.x), "=f"(r.y) : "l"(v));
    return r;
}
#define FMA2(d, a, b, c) asm("fma.rn.f32x2 %0, %1, %2, %3;" : "=l"(d) : "l"(a), "l"(b), "l"(c))

// =================== K1: hw = h @ W  + fused hb = h . b_proj  ===================
// R5 staging/compute kept VERBATIM; bias FFMAs added on the already-loaded registers
// (R6 evidence: this exact reduction left rel_err bit-identical at 1.17429e-07).
__global__ void __launch_bounds__(256) k1_hw(const float* __restrict__ h,
                                             const float* __restrict__ w,
                                             const float* __restrict__ bp) {
    __shared__ float hS[64*68];   // [r][d] stride 68
    __shared__ float wS[64*84];   // [d][m] stride 84
    int tid  = threadIdx.x;
    int row0 = blockIdx.x * 64;
    int tx = tid & 15;
    int ty = tid >> 4;
    float acc[4][5];
#pragma unroll
    for (int r = 0; r < 4; r++)
#pragma unroll
        for (int m = 0; m < 5; m++) acc[r][m] = 0.f;

    float bacc[4] = {0.f, 0.f, 0.f, 0.f};
    const float4* bp4 = (const float4*)bp;

    for (int dc = 0; dc < D_; dc += 64) {
#pragma unroll
        for (int k = 0; k < 4; k++) {
            int l = tid + k*256;
            int r = l >> 4, d4 = l & 15;
            float4 v = *(const float4*)&h[(size_t)(row0 + r)*D_ + dc + d4*4];
            *(float4*)&hS[r*68 + d4*4] = v;
            float4 bv = bp4[(dc >> 2) + d4];
            bacc[k] += v.x*bv.x + v.y*bv.y + v.z*bv.z + v.w*bv.w;
        }
#pragma unroll
        for (int k = 0; k < 5; k++) {
            int l = tid + k*256;
            int d = l / 20, m4 = l % 20;
            float4 v = *(const float4*)&w[(size_t)(dc + d)*M_ + m4*4];
            *(float4*)&wS[d*84 + m4*4] = v;
        }
        __syncthreads();
#pragma unroll 8
        for (int d = 0; d < 64; d++) {
            float a0 = hS[(ty*4+0)*68 + d];
            float a1 = hS[(ty*4+1)*68 + d];
            float a2 = hS[(ty*4+2)*68 + d];
            float a3 = hS[(ty*4+3)*68 + d];
#pragma unroll
            for (int m = 0; m < 5; m++) {
                float bv = wS[d*84 + tx*5 + m];
                acc[0][m] += a0*bv; acc[1][m] += a1*bv;
                acc[2][m] += a2*bv; acc[3][m] += a3*bv;
            }
        }
        __syncthreads();
    }
#pragma unroll
    for (int r = 0; r < 4; r++)
#pragma unroll
        for (int m = 0; m < 5; m++)
            g_hw[(size_t)(row0 + ty*4 + r)*M_ + tx*5 + m] = acc[r][m];

    // bias reduce: the 16 threads sharing tid>>4 hold partials for row (tid>>4)+16k
#pragma unroll
    for (int k = 0; k < 4; k++) {
        float s = bacc[k];
        s += __shfl_down_sync(0xffffffffu, s, 8);
        s += __shfl_down_sync(0xffffffffu, s, 4);
        s += __shfl_down_sync(0xffffffffu, s, 2);
        s += __shfl_down_sync(0xffffffffu, s, 1);
        if ((tid & 15) == 0) g_hb[row0 + (tid >> 4) + 16*k] = s;
    }
}

// =================== K2: S[b][j][i] = masked(hw . mel + hb) ===================
// R5 version + early exit for fully-masked i-blocks (i0 >= text_len): the whole
// 128x128 tile is NEGF, so skip staging/GEMM and write the fill directly
// (bit-identical to what the masked GEMM path wrote).
__global__ void __launch_bounds__(256) k2_attn(const float* __restrict__ mel,
                                               const int* __restrict__ tlv,
                                               const int* __restrict__ mlv) {
    extern __shared__ float sm2[];
    float* melS = sm2;            // [80][132]
    float* hwS  = sm2 + 80*132;   // [80][129]
    int b  = blockIdx.z;
    int ml = mlv[b];
    int j0 = blockIdx.y * 128;
    if (j0 >= ml) return;
    int i0  = blockIdx.x * 128;
    int tid = threadIdx.x;
    int tx  = tid & 15;
    int ty  = tid >> 4;
    int tlb = tlv[b];

    if (i0 >= tlb) {              // whole i-block masked: pure NEGF fill
        float4 nf = make_float4(NEGF, NEGF, NEGF, NEGF);
#pragma unroll
        for (int jk = 0; jk < 8; jk++) {
            int j = j0 + ty + 16*jk;
            if (j < ml) {
                float* row = g_S + ((size_t)b*TM_ + j)*TT_ + i0;
                *(float4*)&row[tx*8]     = nf;
                *(float4*)&row[tx*8 + 4] = nf;
            }
        }
        return;
    }

    const float* melB = mel + (size_t)b*M_*TM_;
#pragma unroll
    for (int k = 0; k < 10; k++) {
        int l = tid + k*256;
        int m = l >> 5, j4 = l & 31;
        float4 v = *(const float4*)&melB[(size_t)m*TM_ + j0 + j4*4];
        *(float4*)&melS[m*132 + j4*4] = v;
    }
    const float* hwB = g_hw + (size_t)b*TT_*M_;
#pragma unroll
    for (int k = 0; k < 40; k++) {
        int l = tid + k*256;
        int m = l % 80, ii = l / 80;
        hwS[m*129 + ii] = hwB[(size_t)(i0+ii)*M_ + m];
    }
    __syncthreads();

    ull acc[8][4];
#pragma unroll
    for (int jk = 0; jk < 8; jk++)
#pragma unroll
        for (int p = 0; p < 4; p++) acc[jk][p] = 0ull;

#pragma unroll 2
    for (int m = 0; m < M_; m++) {
        float hv[8];
#pragma unroll
        for (int k = 0; k < 8; k++) hv[k] = hwS[m*129 + tx + 16*k];
        ull hp[4];
#pragma unroll
        for (int p = 0; p < 4; p++) hp[p] = pk2(hv[2*p], hv[2*p+1]);
#pragma unroll
        for (int jk = 0; jk < 8; jk++) {
            float mv = melS[m*132 + ty + 16*jk];
            ull mp = pk2(mv, mv);
#pragma unroll
            for (int p = 0; p < 4; p++) FMA2(acc[jk][p], hp[p], mp, acc[jk][p]);
        }
    }

    float hbv[8];
    bool  msk[8];
#pragma unroll
    for (int k = 0; k < 8; k++) {
        int ig = i0 + tx + 16*k;
        hbv[k] = g_hb[b*TT_ + ig];
        msk[k] = (ig < tlb);
    }
#pragma unroll
    for (int jk = 0; jk < 8; jk++) {
        int j = j0 + ty + 16*jk;
        if (j < ml) {
            float* row = g_S + ((size_t)b*TM_ + j)*TT_ + i0;
#pragma unroll
            for (int p = 0; p < 4; p++) {
                float2 v = upk2(acc[jk][p]);
                int k0 = 2*p, k1 = 2*p + 1;
                row[tx + 16*k0] = msk[k0] ? (v.x + hbv[k0]) : NEGF;
                row[tx + 16*k1] = msk[k1] ? (v.y + hbv[k1]) : NEGF;
            }
        }
    }
}

// =================== K3: MAS DP + backtrack — R5 VERBATIM (measured 253 µs) ===================
__global__ void __launch_bounds__(512) k3_dp(const float* __restrict__ ldp,
                                             const int* __restrict__ tlv,
                                             const int* __restrict__ mlv,
                                             float* __restrict__ out) {
    extern __shared__ unsigned int dsm[];
    unsigned int* ch   = dsm;                         // [512][65]
    float*        bnd  = (float*)(dsm + 512*65);      // [2][16]
    unsigned int* dur  = (unsigned int*)(bnd + 32);   // [512]
    unsigned int* wsum = dur + 512;                   // [16]
    float*        red  = (float*)(wsum + 16);         // [16]

    int b    = blockIdx.x;
    int i    = threadIdx.x;
    int lane = i & 31, wid = i >> 5;
    int tl = tlv[b], ml = mlv[b];
    const float* Sb = g_S + (size_t)b*TM_*TT_;

    float q = (i == 0) ? Sb[0] : NEGF;
    unsigned int cw = 0;
    int p = 0;
    float c[8], n[8];
#pragma unroll
    for (int k = 0; k < 8; k++) {
        int j = 1 + k;
        c[k] = (j < ml) ? Sb[(size_t)j*TT_ + i] : 0.f;
    }

    for (int j0 = 1; j0 < ml; j0 += 8) {
#pragma unroll
        for (int k = 0; k < 8; k++) {          // prefetch next group
            int j = j0 + 8 + k;
            n[k] = (j < ml) ? Sb[(size_t)j*TT_ + i] : 0.f;
        }
#pragma unroll
        for (int k = 0; k < 8; k++) {
            int j = j0 + k;
            if (j < ml) {                       // uniform across block
                if (lane == 31) bnd[p*16 + wid] = q;
                __syncthreads();
                float up = __shfl_up_sync(0xffffffffu, q, 1);
                if (lane == 0) up = (wid == 0) ? NEGF : bnd[p*16 + wid - 1];
                unsigned int take = (up > q) ? 1u : 0u;
                q = c[k] + fmaxf(q, up);
                cw |= take << (j & 31);
                if ((j & 31) == 31) { ch[i*65 + (j >> 5)] = cw; cw = 0; }
                p ^= 1;
            }
        }
#pragma unroll
        for (int k = 0; k < 8; k++) c[k] = n[k];
    }
    if (((ml - 1) & 31) != 31) ch[i*65 + ((ml - 1) >> 5)] = cw;
    dur[i] = 0;
    __syncthreads();

    if (i == 0) {                               // serial CLZ run-scan backtrack
        int ii = tl - 1, j = ml - 1;
        while (j >= 0) {
            if (ii == 0) { dur[0] += (unsigned)(j + 1); break; }
            unsigned int w = ch[ii*65 + (j >> 5)];
            int bit = j & 31;
            if (bit != 31) w &= (2u << bit) - 1u;
            if (w == 0) { dur[ii] += (unsigned)(bit + 1); j -= bit + 1; }
            else {
                int hb = 31 - __clz(w);
                int jp = (j & ~31) + hb;
                dur[ii] += (unsigned)(j - jp + 1);
                ii -= 1;
                j = jp - 1;
            }
        }
    }
    __syncthreads();

    unsigned int d = dur[i];
    out[DUR_OFF + b*TT_ + i] = (float)d;

    // loss partial
    float part = 0.f;
    if (i < tl) {
        float lg = logf(fmaxf((float)d, 1.0f));
        float df = ldp[b*TT_ + i] - lg;
        part = df * df;
    }
#pragma unroll
    for (int o = 16; o; o >>= 1) part += __shfl_down_sync(0xffffffffu, part, o);
    if (lane == 0) red[wid] = part;

    // inclusive scan of dur -> frame index scatter
    unsigned int v = d;
#pragma unroll
    for (int o = 1; o < 32; o <<= 1) {
        unsigned int t = __shfl_up_sync(0xffffffffu, v, o);
        if (lane >= o) v += t;
    }
    if (lane == 31) wsum[wid] = v;
    __syncthreads();
    if (i < 16) {
        unsigned int s = wsum[i];
#pragma unroll
        for (int o = 1; o < 16; o <<= 1) {
            unsigned int t = __shfl_up_sync(0x0000ffffu, s, o);
            if ((i & 15) >= o) s += t;
        }
        wsum[i] = s;
        float ls = red[i];
#pragma unroll
        for (int o = 8; o; o >>= 1) ls += __shfl_down_sync(0x0000ffffu, ls, o);
        if (i == 0) { g_lsq[b] = ls; g_lcnt[b] = (float)tl; }
    }
    __syncthreads();
    unsigned int base = (wid == 0) ? 0u : wsum[wid - 1];
    unsigned int cend = base + v;
    unsigned int cstart = cend - d;
    for (unsigned int j = cstart; j < cend; j++) g_idx[b*TM_ + j] = i;
}

// =================== K5: length-regulate expansion (+ fused loss reduce) ===================
__global__ void __launch_bounds__(256) k5_expand(const float* __restrict__ h,
                                                 const int* __restrict__ mlv,
                                                 float* __restrict__ out) {
    if (blockIdx.y == 0 && blockIdx.z == 0 && threadIdx.x < 32) {
        float s = g_lsq[threadIdx.x], cc = g_lcnt[threadIdx.x];
#pragma unroll
        for (int o = 16; o; o >>= 1) {
            s  += __shfl_down_sync(0xffffffffu, s, o);
            cc += __shfl_down_sync(0xffffffffu, cc, o);
        }
        if (threadIdx.x == 0) out[LOSS_OFF] = s / cc;
    }
    int b  = blockIdx.z;
    int j  = blockIdx.y * 2 + (threadIdx.x >> 7);
    int c4 = threadIdx.x & 127;
    int ml = mlv[b];
    float4 v;
    if (j < ml) {
        int idx = g_idx[b*TM_ + j];
        v = *(const float4*)&h[((size_t)(b*TT_ + idx))*D_ + c4*4];
    } else {
        v = make_float4(0.f, 0.f, 0.f, 0.f);
    }
    *(float4*)&out[((size_t)(b*TM_ + j))*D_ + c4*4] = v;
}

// =================== host launcher ===================
extern "C" void kernel_launch(void* const* d_in, const int* in_sizes, int n_in,
                              void* d_out, int out_size) {
    const float* h_text = (const float*)d_in[0];   // [32,512,512]
    const float* mel    = (const float*)d_in[1];   // [32,80,2048]
    const int*   tl     = (const int*)  d_in[2];   // [32]
    const int*   mlv    = (const int*)  d_in[3];   // [32]
    const float* w_proj = (const float*)d_in[4];   // [512,80]
    const float* b_proj = (const float*)d_in[5];   // [512]
    const float* ldp    = (const float*)d_in[6];   // [32,512]
    float* out = (float*)d_out;

    const int K2_SMEM = (80*132 + 80*129) * 4;                        // 83520
    const int K3_SMEM = (512*65 + 512 + 16 + 16) * 4 + 32 * 4;        // 135456
    cudaFuncSetAttribute(k2_attn, cudaFuncAttributeMaxDynamicSharedMemorySize, K2_SMEM);
    cudaFuncSetAttribute(k3_dp,   cudaFuncAttributeMaxDynamicSharedMemorySize, K3_SMEM);

    k1_hw<<<256, 256>>>(h_text, w_proj, b_proj);                // launch 1 (hb fused)
    k2_attn<<<dim3(4, 16, 32), 256, K2_SMEM>>>(mel, tl, mlv);   // launch 2
    k3_dp<<<32, 512, K3_SMEM>>>(ldp, tl, mlv, out);             // launch 3
    k5_expand<<<dim3(1, 1024, 32), 256>>>(h_text, mlv, out);    // launch 4
}

// round 15
// speedup vs baseline: 2.8220x; 1.0189x over previous
#include <cuda_runtime.h>
#include <math.h>

#define B_   32
#define TT_  512
#define TM_  2048
#define D_   512
#define M_   80
#define NEGF (-1e9f)

#define HEXP_ELEMS (B_*TM_*D_)       /* 33554432 */
#define LOSS_OFF   HEXP_ELEMS
#define DUR_OFF    (HEXP_ELEMS + 1)

typedef unsigned long long ull;

// ------------------- device scratch (no allocation allowed) -------------------
__device__ float g_hw[B_*TT_*M_];         // [b*Tt+i][80] = h @ W
__device__ float g_hb[B_*TT_];            // h @ b_proj
__device__ float g_S[(size_t)B_*TM_*TT_]; // [b][j][i] masked scores (128 MB)
__device__ int   g_idx[B_*TM_];           // frame -> token index
__device__ float g_lsq[B_];
__device__ float g_lcnt[B_];

// ------------------- f32x2 helpers -------------------
__device__ __forceinline__ ull pk2(float x, float y) {
    ull r;
    asm("mov.b64 %0, {%1,%2};" : "=l"(r) : "f"(x), "f"(y));
    return r;
}
__device__ __forceinline__ float2 upk2(ull v) {
    float2 r;
    asm("mov.b64 {%0,%1}, %2;" : "=f"(r.x), "=f"(r.y) : "l"(v));
    return r;
}
#define FMA2(d, a, b, c) asm("fma.rn.f32x2 %0, %1, %2, %3;" : "=l"(d) : "l"(a), "l"(b), "l"(c))

// =================== K1: hw = h @ W  + fused hb = h . b_proj  (frozen R14) ===================
__global__ void __launch_bounds__(256) k1_hw(const float* __restrict__ h,
                                             const float* __restrict__ w,
                                             const float* __restrict__ bp) {
    __shared__ float hS[64*68];   // [r][d] stride 68
    __shared__ float wS[64*84];   // [d][m] stride 84
    int tid  = threadIdx.x;
    int row0 = blockIdx.x * 64;
    int tx = tid & 15;
    int ty = tid >> 4;
    float acc[4][5];
#pragma unroll
    for (int r = 0; r < 4; r++)
#pragma unroll
        for (int m = 0; m < 5; m++) acc[r][m] = 0.f;

    float bacc[4] = {0.f, 0.f, 0.f, 0.f};
    const float4* bp4 = (const float4*)bp;

    for (int dc = 0; dc < D_; dc += 64) {
#pragma unroll
        for (int k = 0; k < 4; k++) {
            int l = tid + k*256;
            int r = l >> 4, d4 = l & 15;
            float4 v = *(const float4*)&h[(size_t)(row0 + r)*D_ + dc + d4*4];
            *(float4*)&hS[r*68 + d4*4] = v;
            float4 bv = bp4[(dc >> 2) + d4];
            bacc[k] += v.x*bv.x + v.y*bv.y + v.z*bv.z + v.w*bv.w;
        }
#pragma unroll
        for (int k = 0; k < 5; k++) {
            int l = tid + k*256;
            int d = l / 20, m4 = l % 20;
            float4 v = *(const float4*)&w[(size_t)(dc + d)*M_ + m4*4];
            *(float4*)&wS[d*84 + m4*4] = v;
        }
        __syncthreads();
#pragma unroll 8
        for (int d = 0; d < 64; d++) {
            float a0 = hS[(ty*4+0)*68 + d];
            float a1 = hS[(ty*4+1)*68 + d];
            float a2 = hS[(ty*4+2)*68 + d];
            float a3 = hS[(ty*4+3)*68 + d];
#pragma unroll
            for (int m = 0; m < 5; m++) {
                float bv = wS[d*84 + tx*5 + m];
                acc[0][m] += a0*bv; acc[1][m] += a1*bv;
                acc[2][m] += a2*bv; acc[3][m] += a3*bv;
            }
        }
        __syncthreads();
    }
#pragma unroll
    for (int r = 0; r < 4; r++)
#pragma unroll
        for (int m = 0; m < 5; m++)
            g_hw[(size_t)(row0 + ty*4 + r)*M_ + tx*5 + m] = acc[r][m];

#pragma unroll
    for (int k = 0; k < 4; k++) {
        float s = bacc[k];
        s += __shfl_down_sync(0xffffffffu, s, 8);
        s += __shfl_down_sync(0xffffffffu, s, 4);
        s += __shfl_down_sync(0xffffffffu, s, 2);
        s += __shfl_down_sync(0xffffffffu, s, 1);
        if ((tid & 15) == 0) g_hb[row0 + (tid >> 4) + 16*k] = s;
    }
}

// =================== K2: S[b][j][i] = masked(hw . mel + hb)  (frozen R14) ===================
__global__ void __launch_bounds__(256) k2_attn(const float* __restrict__ mel,
                                               const int* __restrict__ tlv,
                                               const int* __restrict__ mlv) {
    extern __shared__ float sm2[];
    float* melS = sm2;            // [80][132]
    float* hwS  = sm2 + 80*132;   // [80][129]
    int b  = blockIdx.z;
    int ml = mlv[b];
    int j0 = blockIdx.y * 128;
    if (j0 >= ml) return;
    int i0  = blockIdx.x * 128;
    int tid = threadIdx.x;
    int tx  = tid & 15;
    int ty  = tid >> 4;
    int tlb = tlv[b];

    if (i0 >= tlb) {              // whole i-block masked: pure NEGF fill
        float4 nf = make_float4(NEGF, NEGF, NEGF, NEGF);
#pragma unroll
        for (int jk = 0; jk < 8; jk++) {
            int j = j0 + ty + 16*jk;
            if (j < ml) {
                float* row = g_S + ((size_t)b*TM_ + j)*TT_ + i0;
                *(float4*)&row[tx*8]     = nf;
                *(float4*)&row[tx*8 + 4] = nf;
            }
        }
        return;
    }

    const float* melB = mel + (size_t)b*M_*TM_;
#pragma unroll
    for (int k = 0; k < 10; k++) {
        int l = tid + k*256;
        int m = l >> 5, j4 = l & 31;
        float4 v = *(const float4*)&melB[(size_t)m*TM_ + j0 + j4*4];
        *(float4*)&melS[m*132 + j4*4] = v;
    }
    const float* hwB = g_hw + (size_t)b*TT_*M_;
#pragma unroll
    for (int k = 0; k < 40; k++) {
        int l = tid + k*256;
        int m = l % 80, ii = l / 80;
        hwS[m*129 + ii] = hwB[(size_t)(i0+ii)*M_ + m];
    }
    __syncthreads();

    ull acc[8][4];
#pragma unroll
    for (int jk = 0; jk < 8; jk++)
#pragma unroll
        for (int p = 0; p < 4; p++) acc[jk][p] = 0ull;

#pragma unroll 2
    for (int m = 0; m < M_; m++) {
        float hv[8];
#pragma unroll
        for (int k = 0; k < 8; k++) hv[k] = hwS[m*129 + tx + 16*k];
        ull hp[4];
#pragma unroll
        for (int p = 0; p < 4; p++) hp[p] = pk2(hv[2*p], hv[2*p+1]);
#pragma unroll
        for (int jk = 0; jk < 8; jk++) {
            float mv = melS[m*132 + ty + 16*jk];
            ull mp = pk2(mv, mv);
#pragma unroll
            for (int p = 0; p < 4; p++) FMA2(acc[jk][p], hp[p], mp, acc[jk][p]);
        }
    }

    float hbv[8];
    bool  msk[8];
#pragma unroll
    for (int k = 0; k < 8; k++) {
        int ig = i0 + tx + 16*k;
        hbv[k] = g_hb[b*TT_ + ig];
        msk[k] = (ig < tlb);
    }
#pragma unroll
    for (int jk = 0; jk < 8; jk++) {
        int j = j0 + ty + 16*jk;
        if (j < ml) {
            float* row = g_S + ((size_t)b*TM_ + j)*TT_ + i0;
#pragma unroll
            for (int p = 0; p < 4; p++) {
                float2 v = upk2(acc[jk][p]);
                int k0 = 2*p, k1 = 2*p + 1;
                row[tx + 16*k0] = msk[k0] ? (v.x + hbv[k0]) : NEGF;
                row[tx + 16*k1] = msk[k1] ? (v.y + hbv[k1]) : NEGF;
            }
        }
    }
}

// =================== K3: MAS DP + backtrack — R5 VERBATIM (measured 253 µs, frozen) ===================
__global__ void __launch_bounds__(512) k3_dp(const float* __restrict__ ldp,
                                             const int* __restrict__ tlv,
                                             const int* __restrict__ mlv,
                                             float* __restrict__ out) {
    extern __shared__ unsigned int dsm[];
    unsigned int* ch   = dsm;                         // [512][65]
    float*        bnd  = (float*)(dsm + 512*65);      // [2][16]
    unsigned int* dur  = (unsigned int*)(bnd + 32);   // [512]
    unsigned int* wsum = dur + 512;                   // [16]
    float*        red  = (float*)(wsum + 16);         // [16]

    int b    = blockIdx.x;
    int i    = threadIdx.x;
    int lane = i & 31, wid = i >> 5;
    int tl = tlv[b], ml = mlv[b];
    const float* Sb = g_S + (size_t)b*TM_*TT_;

    float q = (i == 0) ? Sb[0] : NEGF;
    unsigned int cw = 0;
    int p = 0;
    float c[8], n[8];
#pragma unroll
    for (int k = 0; k < 8; k++) {
        int j = 1 + k;
        c[k] = (j < ml) ? Sb[(size_t)j*TT_ + i] : 0.f;
    }

    for (int j0 = 1; j0 < ml; j0 += 8) {
#pragma unroll
        for (int k = 0; k < 8; k++) {          // prefetch next group
            int j = j0 + 8 + k;
            n[k] = (j < ml) ? Sb[(size_t)j*TT_ + i] : 0.f;
        }
#pragma unroll
        for (int k = 0; k < 8; k++) {
            int j = j0 + k;
            if (j < ml) {                       // uniform across block
                if (lane == 31) bnd[p*16 + wid] = q;
                __syncthreads();
                float up = __shfl_up_sync(0xffffffffu, q, 1);
                if (lane == 0) up = (wid == 0) ? NEGF : bnd[p*16 + wid - 1];
                unsigned int take = (up > q) ? 1u : 0u;
                q = c[k] + fmaxf(q, up);
                cw |= take << (j & 31);
                if ((j & 31) == 31) { ch[i*65 + (j >> 5)] = cw; cw = 0; }
                p ^= 1;
            }
        }
#pragma unroll
        for (int k = 0; k < 8; k++) c[k] = n[k];
    }
    if (((ml - 1) & 31) != 31) ch[i*65 + ((ml - 1) >> 5)] = cw;
    dur[i] = 0;
    __syncthreads();

    if (i == 0) {                               // serial CLZ run-scan backtrack
        int ii = tl - 1, j = ml - 1;
        while (j >= 0) {
            if (ii == 0) { dur[0] += (unsigned)(j + 1); break; }
            unsigned int w = ch[ii*65 + (j >> 5)];
            int bit = j & 31;
            if (bit != 31) w &= (2u << bit) - 1u;
            if (w == 0) { dur[ii] += (unsigned)(bit + 1); j -= bit + 1; }
            else {
                int hb = 31 - __clz(w);
                int jp = (j & ~31) + hb;
                dur[ii] += (unsigned)(j - jp + 1);
                ii -= 1;
                j = jp - 1;
            }
        }
    }
    __syncthreads();

    unsigned int d = dur[i];
    out[DUR_OFF + b*TT_ + i] = (float)d;

    // loss partial
    float part = 0.f;
    if (i < tl) {
        float lg = logf(fmaxf((float)d, 1.0f));
        float df = ldp[b*TT_ + i] - lg;
        part = df * df;
    }
#pragma unroll
    for (int o = 16; o; o >>= 1) part += __shfl_down_sync(0xffffffffu, part, o);
    if (lane == 0) red[wid] = part;

    // inclusive scan of dur -> frame index scatter
    unsigned int v = d;
#pragma unroll
    for (int o = 1; o < 32; o <<= 1) {
        unsigned int t = __shfl_up_sync(0xffffffffu, v, o);
        if (lane >= o) v += t;
    }
    if (lane == 31) wsum[wid] = v;
    __syncthreads();
    if (i < 16) {
        unsigned int s = wsum[i];
#pragma unroll
        for (int o = 1; o < 16; o <<= 1) {
            unsigned int t = __shfl_up_sync(0x0000ffffu, s, o);
            if ((i & 15) >= o) s += t;
        }
        wsum[i] = s;
        float ls = red[i];
#pragma unroll
        for (int o = 8; o; o >>= 1) ls += __shfl_down_sync(0x0000ffffu, ls, o);
        if (i == 0) { g_lsq[b] = ls; g_lcnt[b] = (float)tl; }
    }
    __syncthreads();
    unsigned int base = (wid == 0) ? 0u : wsum[wid - 1];
    unsigned int cend = base + v;
    unsigned int cstart = cend - d;
    for (unsigned int j = cstart; j < cend; j++) g_idx[b*TM_ + j] = i;
}

// =================== K5: expansion — 2 consecutive frames/thread, idx-dedup ===================
// Block 256 threads = 2 groups x 128 lanes; group handles frame pair (jA, jA+1).
// idx is monotone with avg run ~4, so the second gather is skipped ~75% of the time;
// two independent chains double MLP. Output values bit-identical to R14.
__global__ void __launch_bounds__(256) k5_expand(const float* __restrict__ h,
                                                 const int* __restrict__ mlv,
                                                 float* __restrict__ out) {
    if (blockIdx.y == 0 && blockIdx.z == 0 && threadIdx.x < 32) {
        float s = g_lsq[threadIdx.x], cc = g_lcnt[threadIdx.x];
#pragma unroll
        for (int o = 16; o; o >>= 1) {
            s  += __shfl_down_sync(0xffffffffu, s, o);
            cc += __shfl_down_sync(0xffffffffu, cc, o);
        }
        if (threadIdx.x == 0) out[LOSS_OFF] = s / cc;
    }
    int b  = blockIdx.z;
    int g  = threadIdx.x >> 7;                 // frame-pair group within block
    int c4 = threadIdx.x & 127;                // float4 lane within row
    int jA = blockIdx.y * 4 + g * 2;           // frames jA, jA+1
    int jB = jA + 1;
    int ml = mlv[b];

    float4 vA = make_float4(0.f, 0.f, 0.f, 0.f);
    float4 vB = vA;
    int idxA = -1;
    if (jA < ml) {
        idxA = g_idx[b*TM_ + jA];
        vA = *(const float4*)&h[((size_t)(b*TT_ + idxA))*D_ + c4*4];
    }
    if (jB < ml) {
        int idxB = g_idx[b*TM_ + jB];
        vB = (idxB == idxA) ? vA
             : *(const float4*)&h[((size_t)(b*TT_ + idxB))*D_ + c4*4];
    }
    *(float4*)&out[((size_t)(b*TM_ + jA))*D_ + c4*4] = vA;
    *(float4*)&out[((size_t)(b*TM_ + jB))*D_ + c4*4] = vB;
}

// =================== host launcher ===================
extern "C" void kernel_launch(void* const* d_in, const int* in_sizes, int n_in,
                              void* d_out, int out_size) {
    const float* h_text = (const float*)d_in[0];   // [32,512,512]
    const float* mel    = (const float*)d_in[1];   // [32,80,2048]
    const int*   tl     = (const int*)  d_in[2];   // [32]
    const int*   mlv    = (const int*)  d_in[3];   // [32]
    const float* w_proj = (const float*)d_in[4];   // [512,80]
    const float* b_proj = (const float*)d_in[5];   // [512]
    const float* ldp    = (const float*)d_in[6];   // [32,512]
    float* out = (float*)d_out;

    const int K2_SMEM = (80*132 + 80*129) * 4;                        // 83520
    const int K3_SMEM = (512*65 + 512 + 16 + 16) * 4 + 32 * 4;        // 135456
    cudaFuncSetAttribute(k2_attn, cudaFuncAttributeMaxDynamicSharedMemorySize, K2_SMEM);
    cudaFuncSetAttribute(k3_dp,   cudaFuncAttributeMaxDynamicSharedMemorySize, K3_SMEM);

    k1_hw<<<256, 256>>>(h_text, w_proj, b_proj);                // launch 1
    k2_attn<<<dim3(4, 16, 32), 256, K2_SMEM>>>(mel, tl, mlv);   // launch 2
    k3_dp<<<32, 512, K3_SMEM>>>(ldp, tl, mlv, out);             // launch 3
    k5_expand<<<dim3(1, 512, 32), 256>>>(h_text, mlv, out);     // launch 4 (4 frames/block)
}

// round 16
// speedup vs baseline: 2.8951x; 1.0259x over previous
#include <cuda_runtime.h>
#include <math.h>

#define B_   32
#define TT_  512
#define TM_  2048
#define D_   512
#define M_   80
#define NEGF (-1e9f)

#define HEXP_ELEMS (B_*TM_*D_)       /* 33554432 */
#define LOSS_OFF   HEXP_ELEMS
#define DUR_OFF    (HEXP_ELEMS + 1)

typedef unsigned long long ull;

// ------------------- device scratch (no allocation allowed) -------------------
__device__ float g_hw[B_*TT_*M_];         // [b*Tt+i][80] = h @ W
__device__ float g_hb[B_*TT_];            // h @ b_proj
__device__ float g_S[(size_t)B_*TM_*TT_]; // [b][j][i] masked scores (128 MB)
__device__ int   g_idx[B_*TM_];           // frame -> token index
__device__ float g_lsq[B_];
__device__ float g_lcnt[B_];

// ------------------- f32x2 helpers -------------------
__device__ __forceinline__ ull pk2(float x, float y) {
    ull r;
    asm("mov.b64 %0, {%1,%2};" : "=l"(r) : "f"(x), "f"(y));
    return r;
}
__device__ __forceinline__ float2 upk2(ull v) {
    float2 r;
    asm("mov.b64 {%0,%1}, %2;" : "=f"(r.x), "=f"(r.y) : "l"(v));
    return r;
}
#define FMA2(d, a, b, c) asm("fma.rn.f32x2 %0, %1, %2, %3;" : "=l"(d) : "l"(a), "l"(b), "l"(c))

// =================== K1: hw = h @ W  + fused hb = h . b_proj  (frozen R14) ===================
__global__ void __launch_bounds__(256) k1_hw(const float* __restrict__ h,
                                             const float* __restrict__ w,
                                             const float* __restrict__ bp) {
    __shared__ float hS[64*68];   // [r][d] stride 68
    __shared__ float wS[64*84];   // [d][m] stride 84
    int tid  = threadIdx.x;
    int row0 = blockIdx.x * 64;
    int tx = tid & 15;
    int ty = tid >> 4;
    float acc[4][5];
#pragma unroll
    for (int r = 0; r < 4; r++)
#pragma unroll
        for (int m = 0; m < 5; m++) acc[r][m] = 0.f;

    float bacc[4] = {0.f, 0.f, 0.f, 0.f};
    const float4* bp4 = (const float4*)bp;

    for (int dc = 0; dc < D_; dc += 64) {
#pragma unroll
        for (int k = 0; k < 4; k++) {
            int l = tid + k*256;
            int r = l >> 4, d4 = l & 15;
            float4 v = *(const float4*)&h[(size_t)(row0 + r)*D_ + dc + d4*4];
            *(float4*)&hS[r*68 + d4*4] = v;
            float4 bv = bp4[(dc >> 2) + d4];
            bacc[k] += v.x*bv.x + v.y*bv.y + v.z*bv.z + v.w*bv.w;
        }
#pragma unroll
        for (int k = 0; k < 5; k++) {
            int l = tid + k*256;
            int d = l / 20, m4 = l % 20;
            float4 v = *(const float4*)&w[(size_t)(dc + d)*M_ + m4*4];
            *(float4*)&wS[d*84 + m4*4] = v;
        }
        __syncthreads();
#pragma unroll 8
        for (int d = 0; d < 64; d++) {
            float a0 = hS[(ty*4+0)*68 + d];
            float a1 = hS[(ty*4+1)*68 + d];
            float a2 = hS[(ty*4+2)*68 + d];
            float a3 = hS[(ty*4+3)*68 + d];
#pragma unroll
            for (int m = 0; m < 5; m++) {
                float bv = wS[d*84 + tx*5 + m];
                acc[0][m] += a0*bv; acc[1][m] += a1*bv;
                acc[2][m] += a2*bv; acc[3][m] += a3*bv;
            }
        }
        __syncthreads();
    }
#pragma unroll
    for (int r = 0; r < 4; r++)
#pragma unroll
        for (int m = 0; m < 5; m++)
            g_hw[(size_t)(row0 + ty*4 + r)*M_ + tx*5 + m] = acc[r][m];

#pragma unroll
    for (int k = 0; k < 4; k++) {
        float s = bacc[k];
        s += __shfl_down_sync(0xffffffffu, s, 8);
        s += __shfl_down_sync(0xffffffffu, s, 4);
        s += __shfl_down_sync(0xffffffffu, s, 2);
        s += __shfl_down_sync(0xffffffffu, s, 1);
        if ((tid & 15) == 0) g_hb[row0 + (tid >> 4) + 16*k] = s;
    }
}

// =================== K2: S[b][j][i] = masked(hw . mel + hb) ===================
// Adjacent-j pairing: thread (tx,ty) computes j in {j0+2ty, j0+2ty+1} + 32k (k=0..3),
// i in {i0+tx+16ik} (ik=0..7). The mel FMA2 operand pair is two ADJACENT floats in
// melS -> one LDS.64, no packing; hw side is duplicated via pk2. Staging, smem size,
// occupancy, per-element arithmetic order all unchanged from R14 (bit-identical S).
__global__ void __launch_bounds__(256) k2_attn(const float* __restrict__ mel,
                                               const int* __restrict__ tlv,
                                               const int* __restrict__ mlv) {
    extern __shared__ float sm2[];
    float* melS = sm2;            // [80][132]
    float* hwS  = sm2 + 80*132;   // [80][129]
    int b  = blockIdx.z;
    int ml = mlv[b];
    int j0 = blockIdx.y * 128;
    if (j0 >= ml) return;
    int i0  = blockIdx.x * 128;
    int tid = threadIdx.x;
    int tx  = tid & 15;
    int ty  = tid >> 4;
    int tlb = tlv[b];

    if (i0 >= tlb) {              // whole i-block masked: pure NEGF fill
        float4 nf = make_float4(NEGF, NEGF, NEGF, NEGF);
#pragma unroll
        for (int jk = 0; jk < 8; jk++) {
            int j = j0 + ty + 16*jk;
            if (j < ml) {
                float* row = g_S + ((size_t)b*TM_ + j)*TT_ + i0;
                *(float4*)&row[tx*8]     = nf;
                *(float4*)&row[tx*8 + 4] = nf;
            }
        }
        return;
    }

    const float* melB = mel + (size_t)b*M_*TM_;
#pragma unroll
    for (int k = 0; k < 10; k++) {
        int l = tid + k*256;
        int m = l >> 5, j4 = l & 31;
        float4 v = *(const float4*)&melB[(size_t)m*TM_ + j0 + j4*4];
        *(float4*)&melS[m*132 + j4*4] = v;
    }
    const float* hwB = g_hw + (size_t)b*TT_*M_;
#pragma unroll
    for (int k = 0; k < 40; k++) {
        int l = tid + k*256;
        int m = l % 80, ii = l / 80;
        hwS[m*129 + ii] = hwB[(size_t)(i0+ii)*M_ + m];
    }
    __syncthreads();

    ull acc[4][8];                // [j-pair k][i index ik]
#pragma unroll
    for (int k = 0; k < 4; k++)
#pragma unroll
        for (int p = 0; p < 8; p++) acc[k][p] = 0ull;

#pragma unroll 2
    for (int m = 0; m < M_; m++) {
        ull mp[4];
#pragma unroll
        for (int k = 0; k < 4; k++)   // adjacent pair (j0+2ty+32k, +1): one LDS.64
            mp[k] = *(const ull*)&melS[m*132 + 2*ty + 32*k];
        ull hd[8];
#pragma unroll
        for (int ik = 0; ik < 8; ik++) {
            float hv = hwS[m*129 + tx + 16*ik];
            hd[ik] = pk2(hv, hv);
        }
#pragma unroll
        for (int k = 0; k < 4; k++)
#pragma unroll
            for (int ik = 0; ik < 8; ik++)
                FMA2(acc[k][ik], hd[ik], mp[k], acc[k][ik]);
    }

    float hbv[8];
    bool  msk[8];
#pragma unroll
    for (int ik = 0; ik < 8; ik++) {
        int ig = i0 + tx + 16*ik;
        hbv[ik] = g_hb[b*TT_ + ig];
        msk[ik] = (ig < tlb);
    }
#pragma unroll
    for (int k = 0; k < 4; k++) {
        int jlo = j0 + 2*ty + 32*k;
        int jhi = jlo + 1;
        float* rlo = g_S + ((size_t)b*TM_ + jlo)*TT_ + i0;
        float* rhi = g_S + ((size_t)b*TM_ + jhi)*TT_ + i0;
        bool blo = (jlo < ml), bhi = (jhi < ml);
#pragma unroll
        for (int ik = 0; ik < 8; ik++) {
            float2 v = upk2(acc[k][ik]);
            if (blo) rlo[tx + 16*ik] = msk[ik] ? (v.x + hbv[ik]) : NEGF;
            if (bhi) rhi[tx + 16*ik] = msk[ik] ? (v.y + hbv[ik]) : NEGF;
        }
    }
}

// =================== K3: MAS DP + backtrack — R5 VERBATIM (measured 253 µs, frozen) ===================
__global__ void __launch_bounds__(512) k3_dp(const float* __restrict__ ldp,
                                             const int* __restrict__ tlv,
                                             const int* __restrict__ mlv,
                                             float* __restrict__ out) {
    extern __shared__ unsigned int dsm[];
    unsigned int* ch   = dsm;                         // [512][65]
    float*        bnd  = (float*)(dsm + 512*65);      // [2][16]
    unsigned int* dur  = (unsigned int*)(bnd + 32);   // [512]
    unsigned int* wsum = dur + 512;                   // [16]
    float*        red  = (float*)(wsum + 16);         // [16]

    int b    = blockIdx.x;
    int i    = threadIdx.x;
    int lane = i & 31, wid = i >> 5;
    int tl = tlv[b], ml = mlv[b];
    const float* Sb = g_S + (size_t)b*TM_*TT_;

    float q = (i == 0) ? Sb[0] : NEGF;
    unsigned int cw = 0;
    int p = 0;
    float c[8], n[8];
#pragma unroll
    for (int k = 0; k < 8; k++) {
        int j = 1 + k;
        c[k] = (j < ml) ? Sb[(size_t)j*TT_ + i] : 0.f;
    }

    for (int j0 = 1; j0 < ml; j0 += 8) {
#pragma unroll
        for (int k = 0; k < 8; k++) {          // prefetch next group
            int j = j0 + 8 + k;
            n[k] = (j < ml) ? Sb[(size_t)j*TT_ + i] : 0.f;
        }
#pragma unroll
        for (int k = 0; k < 8; k++) {
            int j = j0 + k;
            if (j < ml) {                       // uniform across block
                if (lane == 31) bnd[p*16 + wid] = q;
                __syncthreads();
                float up = __shfl_up_sync(0xffffffffu, q, 1);
                if (lane == 0) up = (wid == 0) ? NEGF : bnd[p*16 + wid - 1];
                unsigned int take = (up > q) ? 1u : 0u;
                q = c[k] + fmaxf(q, up);
                cw |= take << (j & 31);
                if ((j & 31) == 31) { ch[i*65 + (j >> 5)] = cw; cw = 0; }
                p ^= 1;
            }
        }
#pragma unroll
        for (int k = 0; k < 8; k++) c[k] = n[k];
    }
    if (((ml - 1) & 31) != 31) ch[i*65 + ((ml - 1) >> 5)] = cw;
    dur[i] = 0;
    __syncthreads();

    if (i == 0) {                               // serial CLZ run-scan backtrack
        int ii = tl - 1, j = ml - 1;
        while (j >= 0) {
            if (ii == 0) { dur[0] += (unsigned)(j + 1); break; }
            unsigned int w = ch[ii*65 + (j >> 5)];
            int bit = j & 31;
            if (bit != 31) w &= (2u << bit) - 1u;
            if (w == 0) { dur[ii] += (unsigned)(bit + 1); j -= bit + 1; }
            else {
                int hb = 31 - __clz(w);
                int jp = (j & ~31) + hb;
                dur[ii] += (unsigned)(j - jp + 1);
                ii -= 1;
                j = jp - 1;
            }
        }
    }
    __syncthreads();

    unsigned int d = dur[i];
    out[DUR_OFF + b*TT_ + i] = (float)d;

    // loss partial
    float part = 0.f;
    if (i < tl) {
        float lg = logf(fmaxf((float)d, 1.0f));
        float df = ldp[b*TT_ + i] - lg;
        part = df * df;
    }
#pragma unroll
    for (int o = 16; o; o >>= 1) part += __shfl_down_sync(0xffffffffu, part, o);
    if (lane == 0) red[wid] = part;

    // inclusive scan of dur -> frame index scatter
    unsigned int v = d;
#pragma unroll
    for (int o = 1; o < 32; o <<= 1) {
        unsigned int t = __shfl_up_sync(0xffffffffu, v, o);
        if (lane >= o) v += t;
    }
    if (lane == 31) wsum[wid] = v;
    __syncthreads();
    if (i < 16) {
        unsigned int s = wsum[i];
#pragma unroll
        for (int o = 1; o < 16; o <<= 1) {
            unsigned int t = __shfl_up_sync(0x0000ffffu, s, o);
            if ((i & 15) >= o) s += t;
        }
        wsum[i] = s;
        float ls = red[i];
#pragma unroll
        for (int o = 8; o; o >>= 1) ls += __shfl_down_sync(0x0000ffffu, ls, o);
        if (i == 0) { g_lsq[b] = ls; g_lcnt[b] = (float)tl; }
    }
    __syncthreads();
    unsigned int base = (wid == 0) ? 0u : wsum[wid - 1];
    unsigned int cend = base + v;
    unsigned int cstart = cend - d;
    for (unsigned int j = cstart; j < cend; j++) g_idx[b*TM_ + j] = i;
}

// =================== K5: expansion — 4 consecutive frames/thread, chained dedup ===================
// int4 idx load; idx is monotone (avg run ~4) so ~2.3 of 3 follow-up gathers dedup away.
// Output values bit-identical to R15.
__global__ void __launch_bounds__(256) k5_expand(const float* __restrict__ h,
                                                 const int* __restrict__ mlv,
                                                 float* __restrict__ out) {
    if (blockIdx.y == 0 && blockIdx.z == 0 && threadIdx.x < 32) {
        float s = g_lsq[threadIdx.x], cc = g_lcnt[threadIdx.x];
#pragma unroll
        for (int o = 16; o; o >>= 1) {
            s  += __shfl_down_sync(0xffffffffu, s, o);
            cc += __shfl_down_sync(0xffffffffu, cc, o);
        }
        if (threadIdx.x == 0) out[LOSS_OFF] = s / cc;
    }
    int b  = blockIdx.z;
    int g  = threadIdx.x >> 7;                 // frame-quad group within block
    int c4 = threadIdx.x & 127;                // float4 lane within row
    int j0 = blockIdx.y * 8 + g * 4;           // frames j0..j0+3
    int ml = mlv[b];

    int4 idx4 = *(const int4*)&g_idx[b*TM_ + j0];
    const float* hb = h + (size_t)b*TT_*D_;
    float4 z = make_float4(0.f, 0.f, 0.f, 0.f);
    float4 v0 = z, v1 = z, v2 = z, v3 = z;
    if (j0 < ml)
        v0 = *(const float4*)&hb[(size_t)idx4.x*D_ + c4*4];
    if (j0 + 1 < ml)
        v1 = (idx4.y == idx4.x) ? v0 : *(const float4*)&hb[(size_t)idx4.y*D_ + c4*4];
    if (j0 + 2 < ml)
        v2 = (idx4.z == idx4.y) ? v1 : *(const float4*)&hb[(size_t)idx4.z*D_ + c4*4];
    if (j0 + 3 < ml)
        v3 = (idx4.w == idx4.z) ? v2 : *(const float4*)&hb[(size_t)idx4.w*D_ + c4*4];

    float* ob = out + ((size_t)(b*TM_ + j0))*D_ + c4*4;
    *(float4*)(ob)          = v0;
    *(float4*)(ob + D_)     = v1;
    *(float4*)(ob + 2*D_)   = v2;
    *(float4*)(ob + 3*D_)   = v3;
}

// =================== host launcher ===================
extern "C" void kernel_launch(void* const* d_in, const int* in_sizes, int n_in,
                              void* d_out, int out_size) {
    const float* h_text = (const float*)d_in[0];   // [32,512,512]
    const float* mel    = (const float*)d_in[1];   // [32,80,2048]
    const int*   tl     = (const int*)  d_in[2];   // [32]
    const int*   mlv    = (const int*)  d_in[3];   // [32]
    const float* w_proj = (const float*)d_in[4];   // [512,80]
    const float* b_proj = (const float*)d_in[5];   // [512]
    const float* ldp    = (const float*)d_in[6];   // [32,512]
    float* out = (float*)d_out;

    const int K2_SMEM = (80*132 + 80*129) * 4;                        // 83520
    const int K3_SMEM = (512*65 + 512 + 16 + 16) * 4 + 32 * 4;        // 135456
    cudaFuncSetAttribute(k2_attn, cudaFuncAttributeMaxDynamicSharedMemorySize, K2_SMEM);
    cudaFuncSetAttribute(k3_dp,   cudaFuncAttributeMaxDynamicSharedMemorySize, K3_SMEM);

    k1_hw<<<256, 256>>>(h_text, w_proj, b_proj);                // launch 1
    k2_attn<<<dim3(4, 16, 32), 256, K2_SMEM>>>(mel, tl, mlv);   // launch 2
    k3_dp<<<32, 512, K3_SMEM>>>(ldp, tl, mlv, out);             // launch 3
    k5_expand<<<dim3(1, 256, 32), 256>>>(h_text, mlv, out);     // launch 4 (8 frames/block)
}